// round 3
// baseline (speedup 1.0000x reference)
#include <cuda_runtime.h>
#include <math.h>

// Problem dims
#define BB   2
#define SS   2048
#define HID  512
#define NHH  8
#define DD   64

// ---------------- scratch (static device globals; no allocation) ----------------
__device__ float g_qh[(size_t)BB * SS * HID];                 // [B,S,H*D] layout
__device__ float g_kh[(size_t)BB * SS * HID];
__device__ float g_vh[(size_t)BB * SS * HID];
__device__ float g_X [(size_t)BB * NHH * SS * SS];            // masked scaled scores
__device__ float g_Y [(size_t)BB * NHH * SS * SS];            // X @ w, then softmax in-place
__device__ float g_O [(size_t)BB * SS * HID];                 // attention output, [B,S,H*D]

// ---------------- generic batched GEMM ----------------
// C[m,n] = sum_k A[m,k] * Bop(k,n)  (+ bias[n])
//   BT=true : B is [N,K] row-major (NT gemm, weights)
//   BT=false: B is [K,N] row-major (NN gemm)
// Per-z offsets: off = (z/zdiv)*outer + (z%zdiv)*inner  for each of A,B,C.
// Tile 128x128x16, 256 threads, 8x8 per-thread microtile.
template <bool BT, bool BIAS>
__global__ __launch_bounds__(256)
void gemm128(const float* __restrict__ A, const float* __restrict__ Bm,
             const float* __restrict__ bias, float* __restrict__ C,
             int M, int N, int K, int lda, int ldb, int ldc,
             int zdiv,
             size_t aO, size_t aI, size_t bO, size_t bI, size_t cO, size_t cI)
{
    const int z = blockIdx.z;
    A  += (size_t)(z / zdiv) * aO + (size_t)(z % zdiv) * aI;
    Bm += (size_t)(z / zdiv) * bO + (size_t)(z % zdiv) * bI;
    C  += (size_t)(z / zdiv) * cO + (size_t)(z % zdiv) * cI;

    __shared__ float As[16][132];   // [k][m], pad 4 (132*4B = 528B, 16B aligned rows)
    __shared__ float Bs[16][132];   // [k][n]

    const int tid = threadIdx.x;
    const int tx  = tid & 15;       // n dir
    const int ty  = tid >> 4;       // m dir
    const int m0  = blockIdx.y * 128;
    const int n0  = blockIdx.x * 128;

    float acc[8][8];
#pragma unroll
    for (int i = 0; i < 8; i++)
#pragma unroll
        for (int j = 0; j < 8; j++) acc[i][j] = 0.0f;

    for (int k0 = 0; k0 < K; k0 += 16) {
        // ---- load A tile (transpose into As[k][m]) ----
        {
            const int r  = tid >> 2;            // 0..63
            const int kq = (tid & 3) * 4;       // 0,4,8,12
#pragma unroll
            for (int half = 0; half < 2; half++) {
                const int row = r + half * 64;
                const int gm  = m0 + row;
                float4 v = make_float4(0.f, 0.f, 0.f, 0.f);
                if (gm < M)
                    v = *(const float4*)(A + (size_t)gm * lda + k0 + kq);
                As[kq + 0][row] = v.x;
                As[kq + 1][row] = v.y;
                As[kq + 2][row] = v.z;
                As[kq + 3][row] = v.w;
            }
        }
        // ---- load B tile ----
        if (BT) {
            const int r  = tid >> 2;
            const int kq = (tid & 3) * 4;
#pragma unroll
            for (int half = 0; half < 2; half++) {
                const int row = r + half * 64;
                const int gn  = n0 + row;
                float4 v = make_float4(0.f, 0.f, 0.f, 0.f);
                if (gn < N)
                    v = *(const float4*)(Bm + (size_t)gn * ldb + k0 + kq);
                Bs[kq + 0][row] = v.x;
                Bs[kq + 1][row] = v.y;
                Bs[kq + 2][row] = v.z;
                Bs[kq + 3][row] = v.w;
            }
        } else {
            const int kr = tid >> 4;            // 0..15
            const int nq = (tid & 15) * 4;      // 0..60
#pragma unroll
            for (int half = 0; half < 2; half++) {
                const int col = nq + half * 64;
                const int gn  = n0 + col;
                float4 v = make_float4(0.f, 0.f, 0.f, 0.f);
                if (gn < N)
                    v = *(const float4*)(Bm + (size_t)(k0 + kr) * ldb + gn);
                Bs[kr][col + 0] = v.x;
                Bs[kr][col + 1] = v.y;
                Bs[kr][col + 2] = v.z;
                Bs[kr][col + 3] = v.w;
            }
        }
        __syncthreads();

        // ---- compute ----
#pragma unroll
        for (int kk = 0; kk < 16; kk++) {
            float a[8], b[8];
            *(float4*)&a[0] = *(const float4*)&As[kk][ty * 4];
            *(float4*)&a[4] = *(const float4*)&As[kk][64 + ty * 4];
            *(float4*)&b[0] = *(const float4*)&Bs[kk][tx * 4];
            *(float4*)&b[4] = *(const float4*)&Bs[kk][64 + tx * 4];
#pragma unroll
            for (int i = 0; i < 8; i++)
#pragma unroll
                for (int j = 0; j < 8; j++)
                    acc[i][j] = fmaf(a[i], b[j], acc[i][j]);
        }
        __syncthreads();
    }

    // ---- store ----
#pragma unroll
    for (int i = 0; i < 8; i++) {
        const int lm = (i < 4) ? (ty * 4 + i) : (64 + ty * 4 + i - 4);
        const int gm = m0 + lm;
        if (gm >= M) continue;
#pragma unroll
        for (int j = 0; j < 8; j++) {
            const int ln = (j < 4) ? (tx * 4 + j) : (64 + tx * 4 + j - 4);
            const int gn = n0 + ln;
            if (gn >= N) continue;
            float r = acc[i][j];
            if (BIAS) r += bias[gn];
            C[(size_t)gm * ldc + gn] = r;
        }
    }
}

// ---------------- scores: X[b,h,q,k] = mask ? 0 : (scale * qh.kh + bias) ----------------
// 64x64 tile over (q,k), K-dim = D = 64, 256 threads, 4x4 microtile.
__global__ __launch_bounds__(256)
void scores_kernel(const float* __restrict__ qh, const float* __restrict__ kh,
                   const float* __restrict__ attn_bias, const unsigned* __restrict__ mask,
                   float* __restrict__ X)
{
    const int bh = blockIdx.z;            // b*NH + h
    const int b  = bh >> 3;
    const int h  = bh & 7;
    const int q0 = blockIdx.y * 64;
    const int k0 = blockIdx.x * 64;

    __shared__ float qs[64][68];
    __shared__ float ks[64][68];

    const int tid = threadIdx.x;
    // load 64x64 tiles (d contiguous in [B,S,H*D] layout)
#pragma unroll
    for (int i = 0; i < 4; i++) {
        const int row = (tid >> 4) + i * 16;
        const int dq  = (tid & 15) * 4;
        *(float4*)&qs[row][dq] =
            *(const float4*)(qh + (size_t)(b * SS + q0 + row) * HID + h * DD + dq);
        *(float4*)&ks[row][dq] =
            *(const float4*)(kh + (size_t)(b * SS + k0 + row) * HID + h * DD + dq);
    }
    __syncthreads();

    const int tx = tid & 15;
    const int ty = tid >> 4;
    float acc[4][4];
#pragma unroll
    for (int i = 0; i < 4; i++)
#pragma unroll
        for (int j = 0; j < 4; j++) acc[i][j] = 0.0f;

    for (int d0 = 0; d0 < 64; d0 += 4) {
        float4 av[4], bv[4];
#pragma unroll
        for (int m = 0; m < 4; m++) av[m] = *(const float4*)&qs[ty * 4 + m][d0];
#pragma unroll
        for (int n = 0; n < 4; n++) bv[n] = *(const float4*)&ks[tx * 4 + n][d0];
#pragma unroll
        for (int m = 0; m < 4; m++)
#pragma unroll
            for (int n = 0; n < 4; n++)
                acc[m][n] += av[m].x * bv[n].x + av[m].y * bv[n].y +
                             av[m].z * bv[n].z + av[m].w * bv[n].w;
    }

    const float scale = 0.125f;  // D^-0.5 = 1/8
#pragma unroll
    for (int m = 0; m < 4; m++) {
        const int gq = q0 + ty * 4 + m;
#pragma unroll
        for (int n = 0; n < 4; n++) {
            const int gk = k0 + tx * 4 + n;
            const unsigned mv = mask[((size_t)b * SS + gq) * SS + gk];
            float v;
            if (mv) {
                v = 0.0f;
            } else {
                v = scale * acc[m][n] +
                    attn_bias[((size_t)bh * SS + gq) * SS + gk];
            }
            X[((size_t)bh * SS + gq) * SS + gk] = v;
        }
    }
}

// ---------------- softmax over last dim (row length S=2048), in-place ----------------
__global__ __launch_bounds__(256)
void softmax_kernel(float* __restrict__ Y)
{
    float* p = Y + (size_t)blockIdx.x * SS;
    const int tid = threadIdx.x;

    float v[8];
    float mx = -1e30f;
#pragma unroll
    for (int i = 0; i < 8; i++) {
        v[i] = p[tid + i * 256];
        mx = fmaxf(mx, v[i]);
    }
    // block max
    __shared__ float sh[8];
#pragma unroll
    for (int o = 16; o > 0; o >>= 1) mx = fmaxf(mx, __shfl_xor_sync(0xffffffffu, mx, o));
    if ((tid & 31) == 0) sh[tid >> 5] = mx;
    __syncthreads();
    float bm = sh[0];
#pragma unroll
    for (int i = 1; i < 8; i++) bm = fmaxf(bm, sh[i]);
    __syncthreads();

    float sum = 0.0f;
#pragma unroll
    for (int i = 0; i < 8; i++) {
        v[i] = expf(v[i] - bm);
        sum += v[i];
    }
#pragma unroll
    for (int o = 16; o > 0; o >>= 1) sum += __shfl_xor_sync(0xffffffffu, sum, o);
    if ((tid & 31) == 0) sh[tid >> 5] = sum;
    __syncthreads();
    float bs = 0.0f;
#pragma unroll
    for (int i = 0; i < 8; i++) bs += sh[i];
    const float inv = 1.0f / bs;
#pragma unroll
    for (int i = 0; i < 8; i++) p[tid + i * 256] = v[i] * inv;
}

// ---------------- launch ----------------
extern "C" void kernel_launch(void* const* d_in, const int* in_sizes, int n_in,
                              void* d_out, int out_size)
{
    const float*    q    = (const float*)d_in[0];
    const float*    k    = (const float*)d_in[1];
    const float*    v    = (const float*)d_in[2];
    const float*    bias = (const float*)d_in[3];   // attn_bias [B,NH,S,S]
    const unsigned* mask = (const unsigned*)d_in[4];// bool serialized 4-byte (int32/f32): nonzero=true
    const float*    w    = (const float*)d_in[5];   // [B,S,S]
    const float*    Wq   = (const float*)d_in[6];
    const float*    bq   = (const float*)d_in[7];
    const float*    Wk   = (const float*)d_in[8];
    const float*    bk   = (const float*)d_in[9];
    const float*    Wv   = (const float*)d_in[10];
    const float*    bv   = (const float*)d_in[11];
    const float*    Wo   = (const float*)d_in[12];
    const float*    bo   = (const float*)d_in[13];
    float* out = (float*)d_out;

    float *qh, *kh, *vh, *X, *Y, *O;
    cudaGetSymbolAddress((void**)&qh, g_qh);
    cudaGetSymbolAddress((void**)&kh, g_kh);
    cudaGetSymbolAddress((void**)&vh, g_vh);
    cudaGetSymbolAddress((void**)&X,  g_X);
    cudaGetSymbolAddress((void**)&Y,  g_Y);
    cudaGetSymbolAddress((void**)&O,  g_O);

    const size_t SSs = (size_t)SS * SS;           // 4.19M
    const size_t XB  = (size_t)NHH * SSs;         // per-batch X/Y stride

    // 1) QKV projections: [4096,512] @ W[n,k]^T + b  -> [B,S,H*D]
    {
        dim3 grid(HID / 128, (BB * SS) / 128, 1);
        gemm128<true, true><<<grid, 256>>>(q, Wq, bq, qh,
            BB * SS, HID, HID, HID, HID, HID, 1, 0, 0, 0, 0, 0, 0);
        gemm128<true, true><<<grid, 256>>>(k, Wk, bk, kh,
            BB * SS, HID, HID, HID, HID, HID, 1, 0, 0, 0, 0, 0, 0);
        gemm128<true, true><<<grid, 256>>>(v, Wv, bv, vh,
            BB * SS, HID, HID, HID, HID, HID, 1, 0, 0, 0, 0, 0, 0);
    }

    // 2) scores + bias + mask -> X [B,NH,S,S]
    {
        dim3 grid(SS / 64, SS / 64, BB * NHH);
        scores_kernel<<<grid, 256>>>(qh, kh, bias, mask, X);
    }

    // 3) Y = X @ w   (per batch b: [NH*S, S] @ [S, S], NN)
    {
        dim3 grid(SS / 128, (NHH * SS) / 128, BB);
        gemm128<false, false><<<grid, 256>>>(X, w, nullptr, Y,
            NHH * SS, SS, SS, SS, SS, SS,
            1, XB, 0, SSs, 0, XB, 0);
    }

    // 4) softmax rows of Y in-place
    softmax_kernel<<<BB * NHH * SS, 256>>>(Y);

    // 5) O = P @ vh  (per (b,h): [S,S] @ [S,D] NN; vh/O in [B,S,H*D] layout)
    {
        dim3 grid(1, SS / 128, BB * NHH);
        gemm128<false, false><<<grid, 256>>>(Y, vh, nullptr, O,
            SS, DD, SS, SS, HID, HID,
            8,
            (size_t)NHH * SSs, SSs,            // A: z*S*S
            (size_t)SS * HID, (size_t)DD,      // B: b*S*HID + h*D
            (size_t)SS * HID, (size_t)DD);     // C: same
    }

    // 6) out = O @ Wo^T + bo
    {
        dim3 grid(HID / 128, (BB * SS) / 128, 1);
        gemm128<true, true><<<grid, 256>>>(O, Wo, bo, out,
            BB * SS, HID, HID, HID, HID, HID, 1, 0, 0, 0, 0, 0, 0);
    }
}

// round 5
// speedup vs baseline: 1.6624x; 1.6624x over previous
#include <cuda_runtime.h>
#include <cuda_bf16.h>
#include <cstdint>
#include <math.h>

// Problem dims
#define BB   2
#define SS   2048
#define HID  512
#define NHH  8
#define DD   64

// ---------------- scratch (static device globals; no allocation) ----------------
__device__ float g_qh[(size_t)BB * SS * HID];
__device__ float g_kh[(size_t)BB * SS * HID];
__device__ float g_vh[(size_t)BB * SS * HID];
__device__ __nv_bfloat16 g_Xh[(size_t)BB * NHH * SS * SS];   // hi(bf16) of masked scores
__device__ __nv_bfloat16 g_Xl[(size_t)BB * NHH * SS * SS];   // lo residual
__device__ __nv_bfloat16 g_whT[(size_t)BB * SS * SS];        // w^T hi  [b][l][k]
__device__ __nv_bfloat16 g_wlT[(size_t)BB * SS * SS];        // w^T lo
__device__ float g_Y [(size_t)BB * NHH * SS * SS];           // X@w, softmax in-place
__device__ float g_O [(size_t)BB * SS * HID];

// ================= helpers =================
__device__ __forceinline__ uint32_t smem_u32(const void* p) {
    uint32_t a;
    asm("{ .reg .u64 t; cvta.to.shared.u64 t, %1; cvt.u32.u64 %0, t; }" : "=r"(a) : "l"(p));
    return a;
}
__device__ __forceinline__ uint32_t sw128(uint32_t o) { return o ^ ((o >> 3) & 0x70); }

__device__ __forceinline__ void ldsm4(uint32_t& r0, uint32_t& r1, uint32_t& r2, uint32_t& r3, uint32_t addr) {
    asm volatile("ldmatrix.sync.aligned.m8n8.x4.shared.b16 {%0,%1,%2,%3}, [%4];"
        : "=r"(r0), "=r"(r1), "=r"(r2), "=r"(r3) : "r"(addr));
}
__device__ __forceinline__ void mma16816(float* d, const uint32_t* a, const uint32_t* b) {
    asm volatile("mma.sync.aligned.m16n8k16.row.col.f32.bf16.bf16.f32 "
        "{%0,%1,%2,%3}, {%4,%5,%6,%7}, {%8,%9}, {%0,%1,%2,%3};"
        : "+f"(d[0]), "+f"(d[1]), "+f"(d[2]), "+f"(d[3])
        : "r"(a[0]), "r"(a[1]), "r"(a[2]), "r"(a[3]), "r"(b[0]), "r"(b[1]));
}
__device__ __forceinline__ void cpa16(uint32_t dst, const void* src) {
    asm volatile("cp.async.cg.shared.global [%0], [%1], 16;" :: "r"(dst), "l"(src));
}

// ================= x@w GEMM via mma.sync bf16 (3-term split) =================
// Y[m,n] = sum_k Xh*wh + Xh*wl + Xl*wh, fp32 accum.
// CTA 128x128, 8 warps (4m x 2n), warp tile 32x64, K-chunk 64.
// Stage: Ah(16K) Al(16K) Bh(16K) Bl(16K) = 64KB; 3 stages.
#define XW_STAGE 65536
#define XW_SMEM  (3 * XW_STAGE)
#define XW_NCHUNK 32

__device__ __forceinline__ void xw_load(
    uint32_t sbase, int slot, int chunk,
    const __nv_bfloat16* __restrict__ Xh, const __nv_bfloat16* __restrict__ Xl,
    const __nv_bfloat16* __restrict__ whb, const __nv_bfloat16* __restrict__ wlb,
    int m0, int n0, int tid)
{
    const int row  = tid >> 1;
    const int half = tid & 1;
    const int kk   = chunk * 64 + half * 32;
    const __nv_bfloat16* a1 = Xh  + (size_t)(m0 + row) * SS + kk;
    const __nv_bfloat16* a2 = Xl  + (size_t)(m0 + row) * SS + kk;
    const __nv_bfloat16* b1 = whb + (size_t)(n0 + row) * SS + kk;
    const __nv_bfloat16* b2 = wlb + (size_t)(n0 + row) * SS + kk;
    const uint32_t base = sbase + (uint32_t)slot * XW_STAGE;
    const uint32_t roff = (uint32_t)row * 128 + (uint32_t)half * 64;
#pragma unroll
    for (int c = 0; c < 4; c++) {
        uint32_t s = sw128(roff + c * 16);
        cpa16(base +         s, a1 + c * 8);
        cpa16(base + 16384 + s, a2 + c * 8);
        cpa16(base + 32768 + s, b1 + c * 8);
        cpa16(base + 49152 + s, b2 + c * 8);
    }
}

__device__ __forceinline__ void xw_compute(uint32_t stg, int wm, int wn, int lane,
                                           float acc[2][8][4])
{
    const uint32_t aH = stg, aL = stg + 16384, bH = stg + 32768, bL = stg + 49152;
    const uint32_t a_base = (uint32_t)(wm * 32 + (lane & 15)) * 128 + (uint32_t)((lane >> 4) * 16);
    const uint32_t b_base = (uint32_t)(wn * 64 + (lane & 7) + ((lane >> 4) << 3)) * 128
                          + (uint32_t)(((lane >> 3) & 1) * 16);
#pragma unroll
    for (int ks = 0; ks < 4; ks++) {
        const uint32_t k0b = (uint32_t)ks * 32;
        uint32_t ah[2][4], al[2][4], bh[8][2], bl[8][2];
#pragma unroll
        for (int mb = 0; mb < 2; mb++) {
            uint32_t s = sw128(a_base + (uint32_t)mb * 2048 + k0b);
            ldsm4(ah[mb][0], ah[mb][1], ah[mb][2], ah[mb][3], aH + s);
            ldsm4(al[mb][0], al[mb][1], al[mb][2], al[mb][3], aL + s);
        }
#pragma unroll
        for (int nb2 = 0; nb2 < 4; nb2++) {
            uint32_t s = sw128(b_base + (uint32_t)nb2 * 2048 + k0b);
            uint32_t r0, r1, r2, r3;
            ldsm4(r0, r1, r2, r3, bH + s);
            bh[2 * nb2][0] = r0; bh[2 * nb2][1] = r1;
            bh[2 * nb2 + 1][0] = r2; bh[2 * nb2 + 1][1] = r3;
            ldsm4(r0, r1, r2, r3, bL + s);
            bl[2 * nb2][0] = r0; bl[2 * nb2][1] = r1;
            bl[2 * nb2 + 1][0] = r2; bl[2 * nb2 + 1][1] = r3;
        }
#pragma unroll
        for (int mb = 0; mb < 2; mb++)
#pragma unroll
            for (int nb = 0; nb < 8; nb++) {
                mma16816(acc[mb][nb], ah[mb], bh[nb]);
                mma16816(acc[mb][nb], ah[mb], bl[nb]);
                mma16816(acc[mb][nb], al[mb], bh[nb]);
            }
    }
}

__global__ __launch_bounds__(256, 1)
void xw_mma_kernel(const __nv_bfloat16* __restrict__ Xh, const __nv_bfloat16* __restrict__ Xl,
                   const __nv_bfloat16* __restrict__ whT, const __nv_bfloat16* __restrict__ wlT,
                   float* __restrict__ Y)
{
    extern __shared__ char smem[];
    const uint32_t sbase = smem_u32(smem);
    const int tid  = threadIdx.x;
    const int wid  = tid >> 5;
    const int lane = tid & 31;
    const int wm   = wid & 3;
    const int wn   = wid >> 2;
    const int n0   = blockIdx.x * 128;
    const int m0   = blockIdx.y * 128;
    const int batch = m0 >> 14;                 // 16384 rows per batch
    const __nv_bfloat16* whb = whT + (size_t)batch * SS * SS;
    const __nv_bfloat16* wlb = wlT + (size_t)batch * SS * SS;

    float acc[2][8][4];
#pragma unroll
    for (int i = 0; i < 2; i++)
#pragma unroll
        for (int j = 0; j < 8; j++)
#pragma unroll
            for (int r = 0; r < 4; r++) acc[i][j][r] = 0.0f;

    // prologue
#pragma unroll
    for (int j = 0; j < 3; j++) {
        xw_load(sbase, j, j, Xh, Xl, whb, wlb, m0, n0, tid);
        asm volatile("cp.async.commit_group;" ::: "memory");
    }

    for (int i = 0; i < XW_NCHUNK; i++) {
        const int s = i % 3;
        asm volatile("cp.async.wait_group 2;" ::: "memory");
        __syncthreads();
        xw_compute(sbase + (uint32_t)s * XW_STAGE, wm, wn, lane, acc);
        __syncthreads();
        if (i + 3 < XW_NCHUNK)
            xw_load(sbase, s, i + 3, Xh, Xl, whb, wlb, m0, n0, tid);
        asm volatile("cp.async.commit_group;" ::: "memory");
    }

    // epilogue: store fp32 accumulators
    const int r  = lane >> 2;
    const int c2 = (lane & 3) * 2;
#pragma unroll
    for (int mb = 0; mb < 2; mb++) {
        const int row = m0 + wm * 32 + mb * 16 + r;
#pragma unroll
        for (int nb = 0; nb < 8; nb++) {
            const int col = n0 + wn * 64 + nb * 8 + c2;
            float2 v0 = make_float2(acc[mb][nb][0], acc[mb][nb][1]);
            float2 v1 = make_float2(acc[mb][nb][2], acc[mb][nb][3]);
            *(float2*)(Y + (size_t)row * SS + col)       = v0;
            *(float2*)(Y + (size_t)(row + 8) * SS + col) = v1;
        }
    }
}

// ================= w -> bf16 hi/lo transpose =================
__global__ __launch_bounds__(256)
void convw_kernel(const float* __restrict__ w, __nv_bfloat16* __restrict__ whT, __nv_bfloat16* __restrict__ wlT)
{
    __shared__ float t[32][33];
    const int b  = blockIdx.z;
    const int k0 = blockIdx.y * 32;
    const int l0 = blockIdx.x * 32;
    const float* wb = w + (size_t)b * SS * SS;
    const int tx = threadIdx.x & 31;
    const int ty = threadIdx.x >> 5;     // 0..7
#pragma unroll
    for (int i = 0; i < 4; i++)
        t[ty + 8 * i][tx] = wb[(size_t)(k0 + ty + 8 * i) * SS + l0 + tx];
    __syncthreads();
#pragma unroll
    for (int i = 0; i < 4; i++) {
        float v = t[tx][ty + 8 * i];                     // w[b][k0+tx][l0+ty+8i]
        size_t idx = (size_t)b * SS * SS + (size_t)(l0 + ty + 8 * i) * SS + (k0 + tx);
        __nv_bfloat16 h = __float2bfloat16(v);
        whT[idx] = h;
        wlT[idx] = __float2bfloat16(v - __bfloat162float(h));
    }
}

// ---------------- generic batched fp32 GEMM (projections, PV, out-proj) ----------------
template <bool BT, bool BIAS>
__global__ __launch_bounds__(256)
void gemm128(const float* __restrict__ A, const float* __restrict__ Bm,
             const float* __restrict__ bias, float* __restrict__ C,
             int M, int N, int K, int lda, int ldb, int ldc,
             int zdiv,
             size_t aO, size_t aI, size_t bO, size_t bI, size_t cO, size_t cI)
{
    const int z = blockIdx.z;
    A  += (size_t)(z / zdiv) * aO + (size_t)(z % zdiv) * aI;
    Bm += (size_t)(z / zdiv) * bO + (size_t)(z % zdiv) * bI;
    C  += (size_t)(z / zdiv) * cO + (size_t)(z % zdiv) * cI;

    __shared__ float As[16][132];
    __shared__ float Bs[16][132];

    const int tid = threadIdx.x;
    const int tx  = tid & 15;
    const int ty  = tid >> 4;
    const int m0  = blockIdx.y * 128;
    const int n0  = blockIdx.x * 128;

    float acc[8][8];
#pragma unroll
    for (int i = 0; i < 8; i++)
#pragma unroll
        for (int j = 0; j < 8; j++) acc[i][j] = 0.0f;

    for (int k0 = 0; k0 < K; k0 += 16) {
        {
            const int r  = tid >> 2;
            const int kq = (tid & 3) * 4;
#pragma unroll
            for (int half = 0; half < 2; half++) {
                const int row = r + half * 64;
                const int gm  = m0 + row;
                float4 v = make_float4(0.f, 0.f, 0.f, 0.f);
                if (gm < M)
                    v = *(const float4*)(A + (size_t)gm * lda + k0 + kq);
                As[kq + 0][row] = v.x; As[kq + 1][row] = v.y;
                As[kq + 2][row] = v.z; As[kq + 3][row] = v.w;
            }
        }
        if (BT) {
            const int r  = tid >> 2;
            const int kq = (tid & 3) * 4;
#pragma unroll
            for (int half = 0; half < 2; half++) {
                const int row = r + half * 64;
                const int gn  = n0 + row;
                float4 v = make_float4(0.f, 0.f, 0.f, 0.f);
                if (gn < N)
                    v = *(const float4*)(Bm + (size_t)gn * ldb + k0 + kq);
                Bs[kq + 0][row] = v.x; Bs[kq + 1][row] = v.y;
                Bs[kq + 2][row] = v.z; Bs[kq + 3][row] = v.w;
            }
        } else {
            const int kr = tid >> 4;
            const int nq = (tid & 15) * 4;
#pragma unroll
            for (int half = 0; half < 2; half++) {
                const int col = nq + half * 64;
                const int gn  = n0 + col;
                float4 v = make_float4(0.f, 0.f, 0.f, 0.f);
                if (gn < N)
                    v = *(const float4*)(Bm + (size_t)(k0 + kr) * ldb + gn);
                Bs[kr][col + 0] = v.x; Bs[kr][col + 1] = v.y;
                Bs[kr][col + 2] = v.z; Bs[kr][col + 3] = v.w;
            }
        }
        __syncthreads();

#pragma unroll
        for (int kk = 0; kk < 16; kk++) {
            float a[8], b[8];
            *(float4*)&a[0] = *(const float4*)&As[kk][ty * 4];
            *(float4*)&a[4] = *(const float4*)&As[kk][64 + ty * 4];
            *(float4*)&b[0] = *(const float4*)&Bs[kk][tx * 4];
            *(float4*)&b[4] = *(const float4*)&Bs[kk][64 + tx * 4];
#pragma unroll
            for (int i = 0; i < 8; i++)
#pragma unroll
                for (int j = 0; j < 8; j++)
                    acc[i][j] = fmaf(a[i], b[j], acc[i][j]);
        }
        __syncthreads();
    }

#pragma unroll
    for (int i = 0; i < 8; i++) {
        const int lm = (i < 4) ? (ty * 4 + i) : (64 + ty * 4 + i - 4);
        const int gm = m0 + lm;
        if (gm >= M) continue;
#pragma unroll
        for (int j = 0; j < 8; j++) {
            const int ln = (j < 4) ? (tx * 4 + j) : (64 + tx * 4 + j - 4);
            const int gn = n0 + ln;
            if (gn >= N) continue;
            float r = acc[i][j];
            if (BIAS) r += bias[gn];
            C[(size_t)gm * ldc + gn] = r;
        }
    }
}

// ---------------- scores: write bf16 hi/lo of (mask ? 0 : scale*q.k + bias) ----------------
__global__ __launch_bounds__(256)
void scores_kernel(const float* __restrict__ qh, const float* __restrict__ kh,
                   const float* __restrict__ attn_bias, const unsigned* __restrict__ mask,
                   __nv_bfloat16* __restrict__ Xh, __nv_bfloat16* __restrict__ Xl)
{
    const int bh = blockIdx.z;
    const int b  = bh >> 3;
    const int h  = bh & 7;
    const int q0 = blockIdx.y * 64;
    const int k0 = blockIdx.x * 64;

    __shared__ float qs[64][68];
    __shared__ float ks[64][68];

    const int tid = threadIdx.x;
#pragma unroll
    for (int i = 0; i < 4; i++) {
        const int row = (tid >> 4) + i * 16;
        const int dq  = (tid & 15) * 4;
        *(float4*)&qs[row][dq] =
            *(const float4*)(qh + (size_t)(b * SS + q0 + row) * HID + h * DD + dq);
        *(float4*)&ks[row][dq] =
            *(const float4*)(kh + (size_t)(b * SS + k0 + row) * HID + h * DD + dq);
    }
    __syncthreads();

    const int tx = tid & 15;
    const int ty = tid >> 4;
    float acc[4][4];
#pragma unroll
    for (int i = 0; i < 4; i++)
#pragma unroll
        for (int j = 0; j < 4; j++) acc[i][j] = 0.0f;

    for (int d0 = 0; d0 < 64; d0 += 4) {
        float4 av[4], bv[4];
#pragma unroll
        for (int m = 0; m < 4; m++) av[m] = *(const float4*)&qs[ty * 4 + m][d0];
#pragma unroll
        for (int n = 0; n < 4; n++) bv[n] = *(const float4*)&ks[tx * 4 + n][d0];
#pragma unroll
        for (int m = 0; m < 4; m++)
#pragma unroll
            for (int n = 0; n < 4; n++)
                acc[m][n] += av[m].x * bv[n].x + av[m].y * bv[n].y +
                             av[m].z * bv[n].z + av[m].w * bv[n].w;
    }

    const float scale = 0.125f;
#pragma unroll
    for (int m = 0; m < 4; m++) {
        const int gq = q0 + ty * 4 + m;
#pragma unroll
        for (int n = 0; n < 4; n++) {
            const int gk = k0 + tx * 4 + n;
            const unsigned mv = mask[((size_t)b * SS + gq) * SS + gk];
            float v;
            if (mv) v = 0.0f;
            else    v = scale * acc[m][n] + attn_bias[((size_t)bh * SS + gq) * SS + gk];
            const size_t idx = ((size_t)bh * SS + gq) * SS + gk;
            __nv_bfloat16 hval = __float2bfloat16(v);
            Xh[idx] = hval;
            Xl[idx] = __float2bfloat16(v - __bfloat162float(hval));
        }
    }
}

// ---------------- softmax over last dim (row length 2048), in-place ----------------
__global__ __launch_bounds__(256)
void softmax_kernel(float* __restrict__ Y)
{
    float* p = Y + (size_t)blockIdx.x * SS;
    const int tid = threadIdx.x;

    float v[8];
    float mx = -1e30f;
#pragma unroll
    for (int i = 0; i < 8; i++) {
        v[i] = p[tid + i * 256];
        mx = fmaxf(mx, v[i]);
    }
    __shared__ float sh[8];
#pragma unroll
    for (int o = 16; o > 0; o >>= 1) mx = fmaxf(mx, __shfl_xor_sync(0xffffffffu, mx, o));
    if ((tid & 31) == 0) sh[tid >> 5] = mx;
    __syncthreads();
    float bm = sh[0];
#pragma unroll
    for (int i = 1; i < 8; i++) bm = fmaxf(bm, sh[i]);
    __syncthreads();

    float sum = 0.0f;
#pragma unroll
    for (int i = 0; i < 8; i++) {
        v[i] = expf(v[i] - bm);
        sum += v[i];
    }
#pragma unroll
    for (int o = 16; o > 0; o >>= 1) sum += __shfl_xor_sync(0xffffffffu, sum, o);
    if ((tid & 31) == 0) sh[tid >> 5] = sum;
    __syncthreads();
    float bs = 0.0f;
#pragma unroll
    for (int i = 0; i < 8; i++) bs += sh[i];
    const float inv = 1.0f / bs;
#pragma unroll
    for (int i = 0; i < 8; i++) p[tid + i * 256] = v[i] * inv;
}

// ---------------- launch ----------------
extern "C" void kernel_launch(void* const* d_in, const int* in_sizes, int n_in,
                              void* d_out, int out_size)
{
    const float*    q    = (const float*)d_in[0];
    const float*    k    = (const float*)d_in[1];
    const float*    v    = (const float*)d_in[2];
    const float*    bias = (const float*)d_in[3];
    const unsigned* mask = (const unsigned*)d_in[4];
    const float*    w    = (const float*)d_in[5];
    const float*    Wq   = (const float*)d_in[6];
    const float*    bq   = (const float*)d_in[7];
    const float*    Wk   = (const float*)d_in[8];
    const float*    bk   = (const float*)d_in[9];
    const float*    Wv   = (const float*)d_in[10];
    const float*    bv   = (const float*)d_in[11];
    const float*    Wo   = (const float*)d_in[12];
    const float*    bo   = (const float*)d_in[13];
    float* out = (float*)d_out;

    float *qh, *kh, *vh, *Y, *O;
    __nv_bfloat16 *Xh, *Xl, *whT, *wlT;
    cudaGetSymbolAddress((void**)&qh,  g_qh);
    cudaGetSymbolAddress((void**)&kh,  g_kh);
    cudaGetSymbolAddress((void**)&vh,  g_vh);
    cudaGetSymbolAddress((void**)&Y,   g_Y);
    cudaGetSymbolAddress((void**)&O,   g_O);
    cudaGetSymbolAddress((void**)&Xh,  g_Xh);
    cudaGetSymbolAddress((void**)&Xl,  g_Xl);
    cudaGetSymbolAddress((void**)&whT, g_whT);
    cudaGetSymbolAddress((void**)&wlT, g_wlT);

    cudaFuncSetAttribute(xw_mma_kernel, cudaFuncAttributeMaxDynamicSharedMemorySize, XW_SMEM);

    const size_t SSs = (size_t)SS * SS;

    // 0) w -> bf16 hi/lo transposed
    {
        dim3 grid(SS / 32, SS / 32, BB);
        convw_kernel<<<grid, 256>>>(w, whT, wlT);
    }

    // 1) QKV projections
    {
        dim3 grid(HID / 128, (BB * SS) / 128, 1);
        gemm128<true, true><<<grid, 256>>>(q, Wq, bq, qh,
            BB * SS, HID, HID, HID, HID, HID, 1, 0, 0, 0, 0, 0, 0);
        gemm128<true, true><<<grid, 256>>>(k, Wk, bk, kh,
            BB * SS, HID, HID, HID, HID, HID, 1, 0, 0, 0, 0, 0, 0);
        gemm128<true, true><<<grid, 256>>>(v, Wv, bv, vh,
            BB * SS, HID, HID, HID, HID, HID, 1, 0, 0, 0, 0, 0, 0);
    }

    // 2) scores + bias + mask -> Xh/Xl bf16
    {
        dim3 grid(SS / 64, SS / 64, BB * NHH);
        scores_kernel<<<grid, 256>>>(qh, kh, bias, mask, Xh, Xl);
    }

    // 3) Y = X @ w  via mma.sync bf16 3-term split
    {
        dim3 grid(SS / 128, (BB * NHH * SS) / 128, 1);
        xw_mma_kernel<<<grid, 256, XW_SMEM>>>(Xh, Xl, whT, wlT, Y);
    }

    // 4) softmax rows of Y in-place
    softmax_kernel<<<BB * NHH * SS, 256>>>(Y);

    // 5) O = P @ vh
    {
        dim3 grid(1, SS / 128, BB * NHH);
        gemm128<false, false><<<grid, 256>>>(Y, vh, nullptr, O,
            SS, DD, SS, SS, HID, HID,
            8,
            (size_t)NHH * SSs, SSs,
            (size_t)SS * HID, (size_t)DD,
            (size_t)SS * HID, (size_t)DD);
    }

    // 6) out = O @ Wo^T + bo
    {
        dim3 grid(HID / 128, (BB * SS) / 128, 1);
        gemm128<true, true><<<grid, 256>>>(O, Wo, bo, out,
            BB * SS, HID, HID, HID, HID, HID, 1, 0, 0, 0, 0, 0, 0);
    }
}